// round 9
// baseline (speedup 1.0000x reference)
#include <cuda_runtime.h>
#include <math.h>

#define NCLS 1000
#define NV4  250   // 1000 floats = 250 float4 per row
#define CHUNKS 8   // ceil(250/32)

// Monotone float -> u32 map (order-preserving; 0 is the bottom identity)
__device__ __forceinline__ unsigned fmap(float x) {
    int i = __float_as_int(x);
    return (i < 0) ? ~(unsigned)i : ((unsigned)i | 0x80000000u);
}
__device__ __forceinline__ float funmap(unsigned u) {
    int i = (u & 0x80000000u) ? (int)(u & 0x7FFFFFFFu) : ~(int)u;
    return __int_as_float(i);
}

// Self-resetting cross-launch scratch (zero at load; last block re-zeros)
__device__ unsigned g_gmax  = 0;
__device__ unsigned g_count = 0;

__global__ __launch_bounds__(256, 6) void margin_kernel(
    const float* __restrict__ o1, const float* __restrict__ o2,
    const float* __restrict__ o3, const float* __restrict__ o4,
    const float* __restrict__ mim, const int* __restrict__ targets,
    float* __restrict__ out_max, float* __restrict__ out_thr, int n)
{
    const int lane = threadIdx.x & 31;
    const int wid  = threadIdx.x >> 5;
    const int row  = blockIdx.x * 8 + wid;

    __shared__ unsigned s_gmax, s_cnt;
    if (threadIdx.x == 0) { s_gmax = 0u; s_cnt = 0u; }
    __syncthreads();                       // only barrier in the kernel

    const float* mats[5] = {o1, o2, o3, o4, mim};
    float g = -INFINITY;                   // this warp's contribution to max_preds

    if (row < n) {
        const int t     = targets[row];
        const int town  = t >> 2;          // float4 index of target (0..249)
        const int tlane = town & 31;
        const int titer = town >> 5;
        const int tsub  = t & 3;

        float acc[5] = {-INFINITY, -INFINITY, -INFINITY, -INFINITY, -INFINITY};
        float tv[5]  = {0.f, 0.f, 0.f, 0.f, 0.f};  // valid only in owner lane

        const size_t base = (size_t)row * NCLS;

        #pragma unroll 1
        for (int i = 0; i < CHUNKS; i++) {
            const int  idx = i * 32 + lane;
            const bool act = (idx < NV4);
            const bool own = (i == titer) && (lane == tlane);

            float4 v[5];
            #pragma unroll
            for (int m = 0; m < 5; m++)
                if (act)
                    v[m] = __ldcs(reinterpret_cast<const float4*>(mats[m] + base) + idx);

            #pragma unroll
            for (int m = 0; m < 5; m++) {
                float a = -INFINITY, b = -INFINITY, c = -INFINITY, d = -INFINITY;
                if (act) { a = v[m].x; b = v[m].y; c = v[m].z; d = v[m].w; }
                if (own) {                 // capture target, exclude from max
                    float t0 = (tsub == 0) ? a : (tsub == 1) ? b : (tsub == 2) ? c : d;
                    tv[m] = t0;
                    if (tsub == 0) a = -INFINITY;
                    else if (tsub == 1) b = -INFINITY;
                    else if (tsub == 2) c = -INFINITY;
                    else                d = -INFINITY;
                }
                acc[m] = fmaxf(acc[m], fmaxf(fmaxf(a, b), fmaxf(c, d)));
            }
        }

        // ---- warp-level finish: one REDUX per matrix, shuffle target in ----
        const unsigned full = 0xFFFFFFFFu;
        unsigned u[5];
        float tvm[5];
        #pragma unroll
        for (int m = 0; m < 5; m++) {
            u[m]   = __reduce_max_sync(full, fmap(acc[m]));
            tvm[m] = __shfl_sync(full, tv[m], tlane);
        }

        if (lane == 0) {
            float m_excl[5];
            #pragma unroll
            for (int m = 0; m < 5; m++) m_excl[m] = funmap(u[m]);

            // row max over mats 0..3 (restore excluded target element)
            #pragma unroll
            for (int m = 0; m < 4; m++) g = fmaxf(g, fmaxf(m_excl[m], tvm[m]));

            // margin = max(0, tgt - max_excl), /TEMPERATURE(=2) folded in
            float margin[5];
            #pragma unroll
            for (int m = 0; m < 5; m++)
                margin[m] = fmaxf(0.0f, (tvm[m] - m_excl[m]) * 0.5f);

            float mx = margin[0];
            #pragma unroll
            for (int m = 1; m < 5; m++) mx = fmaxf(mx, margin[m]);
            float e[5], s = 0.0f;
            #pragma unroll
            for (int m = 0; m < 5; m++) { e[m] = __expf(margin[m] - mx); s += e[m]; }
            float inv = 1.0f / s;
            float* dst = out_thr + (size_t)row * 5;
            #pragma unroll
            for (int m = 0; m < 5; m++) dst[m] = e[m] * inv;
        }
    }

    // ---- block combine in smem, one global atomic pair per block ----
    if (lane == 0) {
        atomicMax(&s_gmax, fmap(g));
        __threadfence_block();
        unsigned c = atomicAdd(&s_cnt, 1);
        if (c == 7) {                      // last warp of the block
            unsigned bg = atomicMax(&s_gmax, 0u);   // atomic read
            atomicMax(&g_gmax, bg);
            __threadfence();
            unsigned gc = atomicAdd(&g_count, 1);
            if (gc == gridDim.x - 1) {     // last block publishes + resets
                unsigned final_u = atomicMax(&g_gmax, 0u);
                *out_max = funmap(final_u);
                atomicExch(&g_gmax, 0u);
                atomicExch(&g_count, 0u);
            }
        }
    }
}

extern "C" void kernel_launch(void* const* d_in, const int* in_sizes, int n_in,
                              void* d_out, int out_size)
{
    const float* o1  = (const float*)d_in[0];
    const float* o2  = (const float*)d_in[1];
    const float* o3  = (const float*)d_in[2];
    const float* o4  = (const float*)d_in[3];
    const float* mim = (const float*)d_in[4];
    const int*   tgt = (const int*)d_in[5];

    const int n = in_sizes[5];          // 16384 rows
    float* out = (float*)d_out;

    float* out_thr = out + ((size_t)out_size - (size_t)n * 5);
    float* out_max = out;

    const int grid = (n + 7) / 8;       // one warp per row, 8 rows per block
    margin_kernel<<<grid, 256>>>(o1, o2, o3, o4, mim, tgt, out_max, out_thr, n);
}

// round 10
// speedup vs baseline: 1.1238x; 1.1238x over previous
#include <cuda_runtime.h>
#include <math.h>

#define NCLS 1000
#define NV4  250   // 1000 floats = 250 float4 per row

// Monotone float -> u32 map (order-preserving; 0 is the bottom identity)
__device__ __forceinline__ unsigned fmap(float x) {
    int i = __float_as_int(x);
    return (i < 0) ? ~(unsigned)i : ((unsigned)i | 0x80000000u);
}
__device__ __forceinline__ float funmap(unsigned u) {
    int i = (u & 0x80000000u) ? (int)(u & 0x7FFFFFFFu) : ~(int)u;
    return __int_as_float(i);
}

// Self-resetting cross-launch scratch (zero at load; last block re-zeros)
__device__ unsigned g_gmax  = 0;
__device__ unsigned g_count = 0;

__global__ __launch_bounds__(256, 8) void margin_kernel(
    const float* __restrict__ o1, const float* __restrict__ o2,
    const float* __restrict__ o3, const float* __restrict__ o4,
    const float* __restrict__ mim, const int* __restrict__ targets,
    float* __restrict__ out_max, float* __restrict__ out_thr)
{
    const int row = blockIdx.x;
    const int tid = threadIdx.x;
    const int t   = targets[row];           // int32
    const int town = t >> 2, tsub = t & 3;  // owning thread / sub-lane of target

    const float* mats[5] = {o1, o2, o3, o4, mim};

    __shared__ float    s_tgt[5];
    __shared__ unsigned s_red[5][8];
    __shared__ float    s_marg[5];
    __shared__ float    s_rowmax[4];

    // ---- load phase: 5 independent streaming float4 loads per thread ----
    float4 v[5];
    const bool active = (tid < NV4);
    if (active) {
        const size_t base = (size_t)row * NCLS;
        #pragma unroll
        for (int m = 0; m < 5; m++)
            v[m] = __ldcs(reinterpret_cast<const float4*>(mats[m] + base) + tid);
    }

    // ---- per-thread max (excluding target element) + target capture ----
    unsigned u[5];
    const bool own = (tid == town);
    #pragma unroll
    for (int m = 0; m < 5; m++) {
        float a = -INFINITY, b = -INFINITY, c = -INFINITY, d = -INFINITY;
        if (active) { a = v[m].x; b = v[m].y; c = v[m].z; d = v[m].w; }
        float mx = fmaxf(fmaxf(a, b), fmaxf(c, d));
        if (own) {   // one thread per row: capture tgt value, exclude it
            float tv = (tsub == 0) ? a : (tsub == 1) ? b : (tsub == 2) ? c : d;
            s_tgt[m] = tv;
            float ea = (tsub == 0) ? -INFINITY : a;
            float eb = (tsub == 1) ? -INFINITY : b;
            float ec = (tsub == 2) ? -INFINITY : c;
            float ed = (tsub == 3) ? -INFINITY : d;
            mx = fmaxf(fmaxf(ea, eb), fmaxf(ec, ed));
        }
        u[m] = fmap(mx);
    }

    // ---- warp reduction: single REDUX per matrix ----
    #pragma unroll
    for (int m = 0; m < 5; m++)
        u[m] = __reduce_max_sync(0xFFFFFFFFu, u[m]);

    const int warp = tid >> 5, lane = tid & 31;
    if (lane == 0) {
        #pragma unroll
        for (int m = 0; m < 5; m++) s_red[m][warp] = u[m];
    }
    __syncthreads();

    // ---- parallel epilogue: threads 0..4 (warp 0) each finish one matrix ----
    if (tid < 32) {
        if (tid < 5) {
            const int m = tid;
            unsigned um = s_red[m][0];
            #pragma unroll
            for (int w = 1; w < 8; w++) um = max(um, s_red[m][w]);
            float m_excl = funmap(um);
            float tv     = s_tgt[m];
            // margin = max(0, tgt - max_excl), /TEMPERATURE(=2) folded in
            s_marg[m] = fmaxf(0.0f, (tv - m_excl) * 0.5f);
            if (m < 4) s_rowmax[m] = fmaxf(m_excl, tv);  // restore excluded elem
        }
        __syncwarp();

        if (tid == 0) {
            float g = fmaxf(fmaxf(s_rowmax[0], s_rowmax[1]),
                            fmaxf(s_rowmax[2], s_rowmax[3]));

            float margin[5];
            #pragma unroll
            for (int m = 0; m < 5; m++) margin[m] = s_marg[m];

            float mx = margin[0];
            #pragma unroll
            for (int m = 1; m < 5; m++) mx = fmaxf(mx, margin[m]);
            float e[5], s = 0.0f;
            #pragma unroll
            for (int m = 0; m < 5; m++) { e[m] = __expf(margin[m] - mx); s += e[m]; }
            float inv = 1.0f / s;
            float* dst = out_thr + (size_t)row * 5;
            #pragma unroll
            for (int m = 0; m < 5; m++) dst[m] = e[m] * inv;

            // ---- global max: atomic accumulate, last block publishes+resets ----
            atomicMax(&g_gmax, fmap(g));
            __threadfence();
            unsigned c = atomicAdd(&g_count, 1);
            if (c == gridDim.x - 1) {
                unsigned final_u = atomicMax(&g_gmax, 0u);
                *out_max = funmap(final_u);
                atomicExch(&g_gmax, 0u);
                atomicExch(&g_count, 0u);
            }
        }
    }
}

extern "C" void kernel_launch(void* const* d_in, const int* in_sizes, int n_in,
                              void* d_out, int out_size)
{
    const float* o1  = (const float*)d_in[0];
    const float* o2  = (const float*)d_in[1];
    const float* o3  = (const float*)d_in[2];
    const float* o4  = (const float*)d_in[3];
    const float* mim = (const float*)d_in[4];
    const int*   tgt = (const int*)d_in[5];

    const int n = in_sizes[5];          // 16384 rows
    float* out = (float*)d_out;

    float* out_thr = out + ((size_t)out_size - (size_t)n * 5);
    float* out_max = out;

    margin_kernel<<<n, 256>>>(o1, o2, o3, o4, mim, tgt, out_max, out_thr);
}